// round 9
// baseline (speedup 1.0000x reference)
#include <cuda_runtime.h>
#include <cuda_fp16.h>
#include <cstdint>

#define DI __device__ __forceinline__

// ---------------- problem dims ----------------
#define MDIM 8192
#define NDIM 4096
#define KDIM 4096
#define BM 128
#define BN 128
#define BK 64
#define STAGES 5
#define NKT (KDIM / BK)            // 64
#define STAGE_BYTES 32768          // A 16KB + B 16KB
#define B_OFF 16384
#define SM_TILE 1024
#define SMEM_TOTAL (SM_TILE + STAGES * STAGE_BYTES)   // 164864, 1 CTA/SM
#define GRID_GEMM ((MDIM / BM) * (NDIM / BN))  // 2048
#define NTHREADS 320               // 8 consumer warps + 2 producer warps

// scratch (allocation-free rule: __device__ globals)
__device__ __half g_x16[(size_t)MDIM * KDIM];   // 67 MB
__device__ __half g_w16[(size_t)NDIM * KDIM];   // 33.5 MB

// ---------------- PTX helpers (baseline sm_80+ features only) ----------------
DI uint32_t smem_u32(const void* p) {
    uint32_t a;
    asm("{ .reg .u64 t; cvta.to.shared.u64 t, %1; cvt.u32.u64 %0, t; }" : "=r"(a) : "l"(p));
    return a;
}
DI void cp16(uint32_t dst, const void* src) {
    asm volatile("cp.async.cg.shared.global [%0], [%1], 16;" :: "r"(dst), "l"(src) : "memory");
}
DI void mbar_init(uint32_t a, uint32_t cnt) {
    asm volatile("mbarrier.init.shared.b64 [%0], %1;" :: "r"(a), "r"(cnt) : "memory");
}
DI void mbar_arrive(uint32_t a) {
    asm volatile("mbarrier.arrive.shared.b64 _, [%0];" :: "r"(a) : "memory");
}
DI void cp_arrive(uint32_t a) {   // arrive when this thread's prior cp.asyncs complete
    asm volatile("cp.async.mbarrier.arrive.noinc.shared.b64 [%0];" :: "r"(a) : "memory");
}
DI void mbar_wait(uint32_t a, uint32_t phase) {
    asm volatile(
        "{\n\t.reg .pred P;\n"
        "LW_%=:\n\t"
        "mbarrier.try_wait.parity.acquire.cta.shared::cta.b64 P, [%0], %1, 0x989680;\n\t"
        "@P bra.uni LD_%=;\n\t"
        "bra.uni LW_%=;\n"
        "LD_%=:\n\t}"
        :: "r"(a), "r"(phase) : "memory");
}
DI void ldm_x4(uint32_t* r, uint32_t addr) {
    asm volatile("ldmatrix.sync.aligned.m8n8.x4.shared.b16 {%0,%1,%2,%3}, [%4];"
                 : "=r"(r[0]), "=r"(r[1]), "=r"(r[2]), "=r"(r[3]) : "r"(addr));
}
DI void mma16816(float* c, const uint32_t* a, uint32_t b0, uint32_t b1) {
    asm volatile(
        "mma.sync.aligned.m16n8k16.row.col.f32.f16.f16.f32 "
        "{%0,%1,%2,%3}, {%4,%5,%6,%7}, {%8,%9}, {%0,%1,%2,%3};"
        : "+f"(c[0]), "+f"(c[1]), "+f"(c[2]), "+f"(c[3])
        : "r"(a[0]), "r"(a[1]), "r"(a[2]), "r"(a[3]), "r"(b0), "r"(b1));
}

// ============================================================
// Kernel 1: x fp32 -> fp16 (RNE)
// ============================================================
__global__ void cvt_kernel(const float* __restrict__ x) {
    int i = blockIdx.x * blockDim.x + threadIdx.x;   // float4 index, exact cover
    float4 v = reinterpret_cast<const float4*>(x)[i];
    __half2 h0 = __floats2half2_rn(v.x, v.y);
    __half2 h1 = __floats2half2_rn(v.z, v.w);
    uint2 u;
    u.x = *reinterpret_cast<uint32_t*>(&h0);
    u.y = *reinterpret_cast<uint32_t*>(&h1);
    reinterpret_cast<uint2*>(g_x16)[i] = u;
}

// ============================================================
// Kernel 2: w16 = fp16(W + 2 * L @ R)   (LORA_SCALE = 32/16 = 2)
// ============================================================
__global__ void weff_kernel(const float* __restrict__ W, const float* __restrict__ L,
                            const float* __restrict__ R) {
    __shared__ float Rs[16][512];
    __shared__ float Ls[16][16];
    int o0 = blockIdx.x * 16;
    int tid = threadIdx.x;
    {
        int oo = tid >> 4, k = tid & 15;
        Ls[oo][k] = 2.0f * L[(o0 + oo) * 16 + k];
    }
    for (int it = 0; it < 8; it++) {
        int i0 = it * 512;
        __syncthreads();
#pragma unroll
        for (int j = 0; j < 8; j++) {
            int idx = tid + j * 256;          // float4 index into 16x512 tile
            int k = idx >> 7;
            int ii = (idx & 127) << 2;
            *reinterpret_cast<float4*>(&Rs[k][ii]) =
                *reinterpret_cast<const float4*>(&R[(size_t)k * 4096 + i0 + ii]);
        }
        __syncthreads();
        int ii = tid * 2;
#pragma unroll 4
        for (int oo = 0; oo < 16; oo++) {
            int o = o0 + oo;
            float2 w = *reinterpret_cast<const float2*>(&W[(size_t)o * 4096 + i0 + ii]);
            float a0 = w.x, a1 = w.y;
#pragma unroll
            for (int k = 0; k < 16; k++) {
                float lk = Ls[oo][k];
                a0 = fmaf(lk, Rs[k][ii], a0);
                a1 = fmaf(lk, Rs[k][ii + 1], a1);
            }
            *reinterpret_cast<__half2*>(&g_w16[(size_t)o * 4096 + i0 + ii]) =
                __floats2half2_rn(a0, a1);
        }
    }
}

// ============================================================
// Kernel 3: GEMM, warp-specialized.
// 320 threads: warps 0-7 consumers (2Mx4N, warp tile 64x32, frag-DB),
// warps 8-9 producers (all cp.async), 5-stage mbarrier ring.
// ============================================================
__global__ __launch_bounds__(NTHREADS, 1)
void gemm_kernel(const float* __restrict__ bias, float* __restrict__ out) {
    extern __shared__ char smem[];
    uint32_t sb = smem_u32(smem);
    int tid = threadIdx.x;
    int lane = tid & 31, wid = tid >> 5;
    int mi = blockIdx.x >> 5, ni = blockIdx.x & 31;
    int m0 = mi * BM, n0 = ni * BN;

    // mbarriers: full[s] at sb+8s (count=64 producer cp-arrives),
    //            empty[s] at sb+256+8s (count=256 consumer arrives)
    if (tid == 0) {
#pragma unroll
        for (int s = 0; s < STAGES; s++) {
            mbar_init(sb + 8 * s, 64);
            mbar_init(sb + 256 + 8 * s, 256);
        }
    }
    __syncthreads();

    if (wid >= 8) {
        // ================= producer: 64 threads, 2 A rows + 2 B rows each =====
        int pt = tid - 256;                 // 0..63
        int r0 = pt * 2;                    // rows r0, r0+1
        const __half* gaA = g_x16 + (size_t)(m0 + r0) * KDIM;
        const __half* gaB = g_x16 + (size_t)(m0 + r0 + 1) * KDIM;
        const __half* gbA = g_w16 + (size_t)(n0 + r0) * KDIM;
        const __half* gbB = g_w16 + (size_t)(n0 + r0 + 1) * KDIM;
        uint32_t sa0 = sb + SM_TILE + r0 * 128;
        uint32_t sa1 = sa0 + 128;
        uint32_t sb0 = sa0 + B_OFF;
        uint32_t sb1 = sa1 + B_OFF;
        int x0 = r0 & 7, x1 = (r0 + 1) & 7;

        int s = 0, ph = 1;   // fresh empty barriers: parity-1 wait passes immediately
        for (int kt = 0; kt < NKT; kt++) {
            mbar_wait(sb + 256 + 8 * s, ph);
            uint32_t off = (uint32_t)(s * STAGE_BYTES);
            const __half *pa0 = gaA + kt * BK, *pa1 = gaB + kt * BK;
            const __half *pb0 = gbA + kt * BK, *pb1 = gbB + kt * BK;
#pragma unroll
            for (int j = 0; j < 8; j++) {
                uint32_t s0 = (uint32_t)((j ^ x0) * 16), s1 = (uint32_t)((j ^ x1) * 16);
                cp16(sa0 + off + s0, pa0 + j * 8);
                cp16(sa1 + off + s1, pa1 + j * 8);
                cp16(sb0 + off + s0, pb0 + j * 8);
                cp16(sb1 + off + s1, pb1 + j * 8);
            }
            cp_arrive(sb + 8 * s);
            if (++s == STAGES) { s = 0; ph ^= 1; }
        }
        return;
    }

    // ================= consumer: 8 warps, 2M x 4N, warp tile 64x32 ===========
    int wm = wid >> 2;        // 0..1 (M)
    int wn = wid & 3;         // 0..3 (N)

    float acc[4][4][4];
#pragma unroll
    for (int a = 0; a < 4; a++)
#pragma unroll
        for (int b = 0; b < 4; b++)
#pragma unroll
            for (int c = 0; c < 4; c++) acc[a][b][c] = 0.0f;

    int ra = lane & 15, ca = lane >> 4;                    // A: 16 rows x 2 k-chunks
    int rb = (lane & 7) + ((lane >> 4) << 3);              // B: 8+8 n-rows
    int cb2 = (lane >> 3) & 1;                             // B: k-chunk half
    uint32_t abase[4], bbase[2];
    int ax[4], bx[2];
#pragma unroll
    for (int mt = 0; mt < 4; mt++) {
        int row = wm * 64 + mt * 16 + ra;
        abase[mt] = (uint32_t)(SM_TILE + row * 128);
        ax[mt] = row & 7;
    }
#pragma unroll
    for (int bt = 0; bt < 2; bt++) {
        int row = wn * 32 + bt * 16 + rb;
        bbase[bt] = (uint32_t)(SM_TILE + B_OFF + row * 128);
        bx[bt] = row & 7;
    }

    uint32_t af[2][4][4], bf[2][2][4];

#define LOAD_FRAGS(st_, ks_, buf_)                                            \
    do {                                                                      \
        _Pragma("unroll")                                                     \
        for (int mt = 0; mt < 4; mt++)                                        \
            ldm_x4(af[buf_][mt],                                              \
                   (st_) + abase[mt] + (uint32_t)((((ks_)*2 + ca) ^ ax[mt]) * 16)); \
        _Pragma("unroll")                                                     \
        for (int bt = 0; bt < 2; bt++)                                        \
            ldm_x4(bf[buf_][bt],                                              \
                   (st_) + bbase[bt] + (uint32_t)((((ks_)*2 + cb2) ^ bx[bt]) * 16)); \
    } while (0)

#define MMA_ALL(buf_)                                                         \
    do {                                                                      \
        _Pragma("unroll")                                                     \
        for (int mt = 0; mt < 4; mt++)                                        \
            _Pragma("unroll")                                                 \
            for (int nt = 0; nt < 4; nt++)                                    \
                mma16816(acc[mt][nt], af[buf_][mt],                           \
                         bf[buf_][nt >> 1][(nt & 1) * 2],                     \
                         bf[buf_][nt >> 1][(nt & 1) * 2 + 1]);                \
    } while (0)

    int s = 0, ph = 0;
    for (int kt = 0; kt < NKT; kt++) {
        mbar_wait(sb + 8 * s, ph);          // wait stage full
        uint32_t st = sb + (uint32_t)(s * STAGE_BYTES);
        LOAD_FRAGS(st, 0, 0);
#pragma unroll
        for (int ks = 0; ks < 4; ks++) {
            if (ks < 3) LOAD_FRAGS(st, ks + 1, (ks + 1) & 1);
            MMA_ALL(ks & 1);
        }
        mbar_arrive(sb + 256 + 8 * s);      // release stage to producer
        if (++s == STAGES) { s = 0; ph ^= 1; }
    }

    // -------- epilogue: direct float2 stores + bias --------
    int r4 = lane >> 2, c2 = (lane & 3) * 2;
#pragma unroll
    for (int nt = 0; nt < 4; nt++) {
        int n = n0 + wn * 32 + nt * 8 + c2;
        float2 bv = *reinterpret_cast<const float2*>(&bias[n]);
#pragma unroll
        for (int mt = 0; mt < 4; mt++) {
            int m = m0 + wm * 64 + mt * 16 + r4;
            float2 v0 = {acc[mt][nt][0] + bv.x, acc[mt][nt][1] + bv.y};
            float2 v1 = {acc[mt][nt][2] + bv.x, acc[mt][nt][3] + bv.y};
            *reinterpret_cast<float2*>(&out[(size_t)m * NDIM + n]) = v0;
            *reinterpret_cast<float2*>(&out[(size_t)(m + 8) * NDIM + n]) = v1;
        }
    }
}

// ============================================================
// launcher
// ============================================================
extern "C" void kernel_launch(void* const* d_in, const int* in_sizes, int n_in,
                              void* d_out, int out_size) {
    const float* x = (const float*)d_in[0];
    const float* W = (const float*)d_in[1];
    const float* bias = (const float*)d_in[2];
    const float* L = (const float*)d_in[3];
    const float* R = (const float*)d_in[4];
    float* out = (float*)d_out;

    cudaFuncSetAttribute(gemm_kernel, cudaFuncAttributeMaxDynamicSharedMemorySize, SMEM_TOTAL);

    cvt_kernel<<<(MDIM * KDIM) / 4 / 256, 256>>>(x);
    weff_kernel<<<NDIM / 16, 256>>>(W, L, R);
    gemm_kernel<<<GRID_GEMM, NTHREADS, SMEM_TOTAL>>>(bias, out);
}

// round 10
// speedup vs baseline: 1.1752x; 1.1752x over previous
#include <cuda_runtime.h>
#include <cuda_fp16.h>
#include <cstdint>

#define DI __device__ __forceinline__

// ---------------- problem dims ----------------
#define MDIM 8192
#define NDIM 4096
#define KDIM 4096
#define BM 128
#define BN 128
#define BK 64
#define STAGES 3
#define NKT (KDIM / BK)            // 64
#define STAGE_BYTES 32768          // A 16KB + B 16KB
#define B_OFF 16384
#define SMEM_TOTAL (STAGES * STAGE_BYTES)   // 96 KB -> 2 CTAs/SM
#define GRID_GEMM ((MDIM / BM) * (NDIM / BN))  // 2048

// scratch (allocation-free rule: __device__ globals)
__device__ __half g_x16[(size_t)MDIM * KDIM];   // 67 MB
__device__ __half g_w16[(size_t)NDIM * KDIM];   // 33.5 MB

// ---------------- PTX helpers (baseline sm_80+ features only) ----------------
DI uint32_t smem_u32(const void* p) {
    uint32_t a;
    asm("{ .reg .u64 t; cvta.to.shared.u64 t, %1; cvt.u32.u64 %0, t; }" : "=r"(a) : "l"(p));
    return a;
}
DI void cp16(uint32_t dst, const void* src) {
    asm volatile("cp.async.cg.shared.global [%0], [%1], 16;" :: "r"(dst), "l"(src) : "memory");
}
DI void cp_commit() { asm volatile("cp.async.commit_group;" ::: "memory"); }
DI void cp_wait1() { asm volatile("cp.async.wait_group 1;" ::: "memory"); }

DI void ldm_x4(uint32_t* r, uint32_t addr) {
    asm volatile("ldmatrix.sync.aligned.m8n8.x4.shared.b16 {%0,%1,%2,%3}, [%4];"
                 : "=r"(r[0]), "=r"(r[1]), "=r"(r[2]), "=r"(r[3]) : "r"(addr));
}
DI void mma16816(float* c, const uint32_t* a, uint32_t b0, uint32_t b1) {
    asm volatile(
        "mma.sync.aligned.m16n8k16.row.col.f32.f16.f16.f32 "
        "{%0,%1,%2,%3}, {%4,%5,%6,%7}, {%8,%9}, {%0,%1,%2,%3};"
        : "+f"(c[0]), "+f"(c[1]), "+f"(c[2]), "+f"(c[3])
        : "r"(a[0]), "r"(a[1]), "r"(a[2]), "r"(a[3]), "r"(b0), "r"(b1));
}

// ============================================================
// Kernel 1: x fp32 -> fp16 (RNE)
// ============================================================
__global__ void cvt_kernel(const float* __restrict__ x) {
    int i = blockIdx.x * blockDim.x + threadIdx.x;   // float4 index, exact cover
    float4 v = reinterpret_cast<const float4*>(x)[i];
    __half2 h0 = __floats2half2_rn(v.x, v.y);
    __half2 h1 = __floats2half2_rn(v.z, v.w);
    uint2 u;
    u.x = *reinterpret_cast<uint32_t*>(&h0);
    u.y = *reinterpret_cast<uint32_t*>(&h1);
    reinterpret_cast<uint2*>(g_x16)[i] = u;
}

// ============================================================
// Kernel 2: w16 = fp16(W + 2 * L @ R)   (LORA_SCALE = 32/16 = 2)
// ============================================================
__global__ void weff_kernel(const float* __restrict__ W, const float* __restrict__ L,
                            const float* __restrict__ R) {
    __shared__ float Rs[16][512];
    __shared__ float Ls[16][16];
    int o0 = blockIdx.x * 16;
    int tid = threadIdx.x;
    {
        int oo = tid >> 4, k = tid & 15;
        Ls[oo][k] = 2.0f * L[(o0 + oo) * 16 + k];
    }
    for (int it = 0; it < 8; it++) {
        int i0 = it * 512;
        __syncthreads();
#pragma unroll
        for (int j = 0; j < 8; j++) {
            int idx = tid + j * 256;          // float4 index into 16x512 tile
            int k = idx >> 7;
            int ii = (idx & 127) << 2;
            *reinterpret_cast<float4*>(&Rs[k][ii]) =
                *reinterpret_cast<const float4*>(&R[(size_t)k * 4096 + i0 + ii]);
        }
        __syncthreads();
        int ii = tid * 2;
#pragma unroll 4
        for (int oo = 0; oo < 16; oo++) {
            int o = o0 + oo;
            float2 w = *reinterpret_cast<const float2*>(&W[(size_t)o * 4096 + i0 + ii]);
            float a0 = w.x, a1 = w.y;
#pragma unroll
            for (int k = 0; k < 16; k++) {
                float lk = Ls[oo][k];
                a0 = fmaf(lk, Rs[k][ii], a0);
                a1 = fmaf(lk, Rs[k][ii + 1], a1);
            }
            *reinterpret_cast<__half2*>(&g_w16[(size_t)o * 4096 + i0 + ii]) =
                __floats2half2_rn(a0, a1);
        }
    }
}

// ============================================================
// Kernel 3: GEMM  out[m][n] = sum_k x16[m][k]*w16[n][k] + bias[n]
// 256 threads, 8 warps (2 M x 4 N), warp tile 64x32, mma.m16n8k16
// 3-stage cp.async pipeline, 2 CTAs/SM, frag double-buffering,
// register-lean addressing (row&7 == lane-derived, mt/bt-invariant)
// ============================================================
__global__ __launch_bounds__(256, 2)
void gemm_kernel(const float* __restrict__ bias, float* __restrict__ out) {
    extern __shared__ char smem[];
    uint32_t sb = smem_u32(smem);
    int tid = threadIdx.x;
    int lane = tid & 31, wid = tid >> 5;
    int wm = wid >> 2;        // 0..1 (M)
    int wn = wid & 3;         // 0..3 (N)
    int mi = blockIdx.x >> 5, ni = blockIdx.x & 31;
    int m0 = mi * BM, n0 = ni * BN;

    // -------- cp.async tile copy: 128 rows x 64 halves (128B rows), swizzled --------
    int crow = tid >> 1;               // 0..127
    int ccb = (tid & 1) * 4;           // chunk base 0 or 4 (chunks of 8 halves = 16B)
    const __half* ga = g_x16 + (size_t)(m0 + crow) * KDIM + ccb * 8;
    const __half* gb = g_w16 + (size_t)(n0 + crow) * KDIM + ccb * 8;
    uint32_t arow = sb + crow * 128;
    uint32_t sw0 = (uint32_t)(((ccb + 0) ^ (crow & 7)) * 16);
    uint32_t sw1 = (uint32_t)(((ccb + 1) ^ (crow & 7)) * 16);
    uint32_t sw2 = (uint32_t)(((ccb + 2) ^ (crow & 7)) * 16);
    uint32_t sw3 = (uint32_t)(((ccb + 3) ^ (crow & 7)) * 16);

    // ga/gb advance by BK per issued tile
#define COPY_TILE(st)                                                         \
    do {                                                                      \
        uint32_t ab = arow + (st) * STAGE_BYTES;                              \
        cp16(ab + sw0, ga);      cp16(ab + B_OFF + sw0, gb);                  \
        cp16(ab + sw1, ga + 8);  cp16(ab + B_OFF + sw1, gb + 8);              \
        cp16(ab + sw2, ga + 16); cp16(ab + B_OFF + sw2, gb + 16);             \
        cp16(ab + sw3, ga + 24); cp16(ab + B_OFF + sw3, gb + 24);             \
        ga += BK; gb += BK;                                                   \
    } while (0)

    COPY_TILE(0); cp_commit();
    COPY_TILE(1); cp_commit();

    float acc[4][4][4];
#pragma unroll
    for (int a = 0; a < 4; a++)
#pragma unroll
        for (int b = 0; b < 4; b++)
#pragma unroll
            for (int c = 0; c < 4; c++) acc[a][b][c] = 0.0f;

    // ldmatrix addressing: row&7 is mt/bt-invariant (mt*16, wm*64 == 0 mod 8)
    int ra = lane & 15, ca = lane >> 4;                    // A: 16 rows x 2 k-chunks
    int rb = (lane & 7) + ((lane >> 4) << 3);              // B: 8+8 n-rows
    int cb2 = (lane >> 3) & 1;                             // B: k-chunk half
    int axr = ra & 7, bxr = rb & 7;
    uint32_t A0 = (uint32_t)((wm * 64 + ra) * 128);              // + mt*2048
    uint32_t B0 = (uint32_t)(B_OFF + (wn * 32 + rb) * 128);      // + bt*2048

    // double-buffered fragments
    uint32_t af[2][4][4], bf[2][2][4];

#define LOAD_FRAGS(stA_, stB_, ks_, buf_)                                     \
    do {                                                                      \
        uint32_t swa = (uint32_t)((((ks_) * 2 + ca) ^ axr) * 16);             \
        uint32_t swb = (uint32_t)((((ks_) * 2 + cb2) ^ bxr) * 16);            \
        ldm_x4(af[buf_][0], (stA_) + 0 * 2048 + swa);                         \
        ldm_x4(af[buf_][1], (stA_) + 1 * 2048 + swa);                         \
        ldm_x4(af[buf_][2], (stA_) + 2 * 2048 + swa);                         \
        ldm_x4(af[buf_][3], (stA_) + 3 * 2048 + swa);                         \
        ldm_x4(bf[buf_][0], (stB_) + 0 * 2048 + swb);                         \
        ldm_x4(bf[buf_][1], (stB_) + 1 * 2048 + swb);                         \
    } while (0)

#define MMA_ALL(buf_)                                                         \
    do {                                                                      \
        _Pragma("unroll")                                                     \
        for (int mt = 0; mt < 4; mt++)                                        \
            _Pragma("unroll")                                                 \
            for (int nt = 0; nt < 4; nt++)                                    \
                mma16816(acc[mt][nt], af[buf_][mt],                           \
                         bf[buf_][nt >> 1][(nt & 1) * 2],                     \
                         bf[buf_][nt >> 1][(nt & 1) * 2 + 1]);                \
    } while (0)

    int cs = 0, ps = 2;   // compute stage / prefetch stage (mod 3)
    for (int kt = 0; kt < NKT; kt++) {
        cp_wait1();
        __syncthreads();
        uint32_t st = sb + cs * STAGE_BYTES;
        uint32_t stA = st + A0, stB = st + B0;
        // load ks=0 fragments first; cp.async issue below covers their latency
        LOAD_FRAGS(stA, stB, 0, 0);
        if (kt + 2 < NKT) { COPY_TILE(ps); }
        cp_commit();
#pragma unroll
        for (int ks = 0; ks < 4; ks++) {
            if (ks < 3) LOAD_FRAGS(stA, stB, ks + 1, (ks + 1) & 1);  // prefetch next
            MMA_ALL(ks & 1);                                          // consume current
        }
        cs = (cs == 2) ? 0 : cs + 1;
        ps = (ps == 2) ? 0 : ps + 1;
    }

    // -------- epilogue: direct float2 stores + bias --------
    int r4 = lane >> 2, c2 = (lane & 3) * 2;
#pragma unroll
    for (int nt = 0; nt < 4; nt++) {
        int n = n0 + wn * 32 + nt * 8 + c2;
        float2 bv = *reinterpret_cast<const float2*>(&bias[n]);
#pragma unroll
        for (int mt = 0; mt < 4; mt++) {
            int m = m0 + wm * 64 + mt * 16 + r4;
            float2 v0 = {acc[mt][nt][0] + bv.x, acc[mt][nt][1] + bv.y};
            float2 v1 = {acc[mt][nt][2] + bv.x, acc[mt][nt][3] + bv.y};
            *reinterpret_cast<float2*>(&out[(size_t)m * NDIM + n]) = v0;
            *reinterpret_cast<float2*>(&out[(size_t)(m + 8) * NDIM + n]) = v1;
        }
    }
}

// ============================================================
// launcher
// ============================================================
extern "C" void kernel_launch(void* const* d_in, const int* in_sizes, int n_in,
                              void* d_out, int out_size) {
    const float* x = (const float*)d_in[0];
    const float* W = (const float*)d_in[1];
    const float* bias = (const float*)d_in[2];
    const float* L = (const float*)d_in[3];
    const float* R = (const float*)d_in[4];
    float* out = (float*)d_out;

    cudaFuncSetAttribute(gemm_kernel, cudaFuncAttributeMaxDynamicSharedMemorySize, SMEM_TOTAL);

    cvt_kernel<<<(MDIM * KDIM) / 4 / 256, 256>>>(x);
    weff_kernel<<<NDIM / 16, 256>>>(W, L, R);
    gemm_kernel<<<GRID_GEMM, 256, SMEM_TOTAL>>>(bias, out);
}

// round 11
// speedup vs baseline: 1.5089x; 1.2839x over previous
#include <cuda_runtime.h>
#include <cuda_fp16.h>
#include <cstdint>

#define DI __device__ __forceinline__

// ---------------- problem dims ----------------
#define MDIM 8192
#define NDIM 4096
#define KDIM 4096
#define BM 128
#define BN 128
#define BK 64
#define STAGES 3
#define NKT (KDIM / BK)            // 64
#define STAGE_BYTES 32768          // A 16KB + B 16KB
#define B_OFF 16384
#define SMEM_TOTAL (STAGES * STAGE_BYTES)   // 96 KB -> 2 CTAs/SM
#define GRID_GEMM ((MDIM / BM) * (NDIM / BN))  // 2048

// scratch (allocation-free rule: __device__ globals)
__device__ __half g_x16[(size_t)MDIM * KDIM];   // 67 MB
__device__ __half g_w16[(size_t)NDIM * KDIM];   // 33.5 MB

// ---------------- PTX helpers (baseline sm_80+ features only) ----------------
DI uint32_t smem_u32(const void* p) {
    uint32_t a;
    asm("{ .reg .u64 t; cvta.to.shared.u64 t, %1; cvt.u32.u64 %0, t; }" : "=r"(a) : "l"(p));
    return a;
}
DI void cp16(uint32_t dst, const void* src) {
    asm volatile("cp.async.cg.shared.global [%0], [%1], 16;" :: "r"(dst), "l"(src) : "memory");
}
DI void cp_commit() { asm volatile("cp.async.commit_group;" ::: "memory"); }
DI void cp_wait1() { asm volatile("cp.async.wait_group 1;" ::: "memory"); }

DI void ldm_x4(uint32_t* r, uint32_t addr) {
    asm volatile("ldmatrix.sync.aligned.m8n8.x4.shared.b16 {%0,%1,%2,%3}, [%4];"
                 : "=r"(r[0]), "=r"(r[1]), "=r"(r[2]), "=r"(r[3]) : "r"(addr));
}
DI void mma16816(float* c, const uint32_t* a, uint32_t b0, uint32_t b1) {
    asm volatile(
        "mma.sync.aligned.m16n8k16.row.col.f32.f16.f16.f32 "
        "{%0,%1,%2,%3}, {%4,%5,%6,%7}, {%8,%9}, {%0,%1,%2,%3};"
        : "+f"(c[0]), "+f"(c[1]), "+f"(c[2]), "+f"(c[3])
        : "r"(a[0]), "r"(a[1]), "r"(a[2]), "r"(a[3]), "r"(b0), "r"(b1));
}

// ============================================================
// Kernel 1: x fp32 -> fp16 (RNE)
// ============================================================
__global__ void cvt_kernel(const float* __restrict__ x) {
    int i = blockIdx.x * blockDim.x + threadIdx.x;   // float4 index, exact cover
    float4 v = reinterpret_cast<const float4*>(x)[i];
    __half2 h0 = __floats2half2_rn(v.x, v.y);
    __half2 h1 = __floats2half2_rn(v.z, v.w);
    uint2 u;
    u.x = *reinterpret_cast<uint32_t*>(&h0);
    u.y = *reinterpret_cast<uint32_t*>(&h1);
    reinterpret_cast<uint2*>(g_x16)[i] = u;
}

// ============================================================
// Kernel 2: w16 = fp16(W + 2 * L @ R)   (LORA_SCALE = 32/16 = 2)
// ============================================================
__global__ void weff_kernel(const float* __restrict__ W, const float* __restrict__ L,
                            const float* __restrict__ R) {
    __shared__ float Rs[16][512];
    __shared__ float Ls[16][16];
    int o0 = blockIdx.x * 16;
    int tid = threadIdx.x;
    {
        int oo = tid >> 4, k = tid & 15;
        Ls[oo][k] = 2.0f * L[(o0 + oo) * 16 + k];
    }
    for (int it = 0; it < 8; it++) {
        int i0 = it * 512;
        __syncthreads();
#pragma unroll
        for (int j = 0; j < 8; j++) {
            int idx = tid + j * 256;          // float4 index into 16x512 tile
            int k = idx >> 7;
            int ii = (idx & 127) << 2;
            *reinterpret_cast<float4*>(&Rs[k][ii]) =
                *reinterpret_cast<const float4*>(&R[(size_t)k * 4096 + i0 + ii]);
        }
        __syncthreads();
        int ii = tid * 2;
#pragma unroll 4
        for (int oo = 0; oo < 16; oo++) {
            int o = o0 + oo;
            float2 w = *reinterpret_cast<const float2*>(&W[(size_t)o * 4096 + i0 + ii]);
            float a0 = w.x, a1 = w.y;
#pragma unroll
            for (int k = 0; k < 16; k++) {
                float lk = Ls[oo][k];
                a0 = fmaf(lk, Rs[k][ii], a0);
                a1 = fmaf(lk, Rs[k][ii + 1], a1);
            }
            *reinterpret_cast<__half2*>(&g_w16[(size_t)o * 4096 + i0 + ii]) =
                __floats2half2_rn(a0, a1);
        }
    }
}

// ============================================================
// Kernel 3: GEMM  out[m][n] = sum_k x16[m][k]*w16[n][k] + bias[n]
// 256 threads, 8 warps (2 M x 4 N), warp tile 64x32, mma.m16n8k16
// 3-stage cp.async pipeline, 2 CTAs/SM, frag double-buffering,
// cp.async spread across the ks loop (smooth port/LSU usage)
// ============================================================
__global__ __launch_bounds__(256, 2)
void gemm_kernel(const float* __restrict__ bias, float* __restrict__ out) {
    extern __shared__ char smem[];
    uint32_t sb = smem_u32(smem);
    int tid = threadIdx.x;
    int lane = tid & 31, wid = tid >> 5;
    int wm = wid >> 2;        // 0..1 (M)
    int wn = wid & 3;         // 0..3 (N)
    int mi = blockIdx.x >> 5, ni = blockIdx.x & 31;
    int m0 = mi * BM, n0 = ni * BN;

    // -------- cp.async tile copy: 128 rows x 64 halves (128B rows), swizzled --------
    int crow = tid >> 1;               // 0..127
    int ccb = (tid & 1) * 4;           // chunk base 0 or 4 (chunks of 8 halves = 16B)
    const __half* ga0 = g_x16 + (size_t)(m0 + crow) * KDIM + ccb * 8;
    const __half* gb0 = g_w16 + (size_t)(n0 + crow) * KDIM + ccb * 8;
    uint32_t arow = sb + crow * 128;

#define COPY_TILE(kt, st)                                                     \
    do {                                                                      \
        const __half* ga = ga0 + (kt) * BK;                                   \
        const __half* gb = gb0 + (kt) * BK;                                   \
        uint32_t ab = arow + (st) * STAGE_BYTES;                              \
        _Pragma("unroll")                                                     \
        for (int j = 0; j < 4; j++) {                                         \
            uint32_t so = (uint32_t)(((ccb + j) ^ (crow & 7)) * 16);          \
            cp16(ab + so, ga + j * 8);                                        \
            cp16(ab + B_OFF + so, gb + j * 8);                                \
        }                                                                     \
    } while (0)

    COPY_TILE(0, 0); cp_commit();
    COPY_TILE(1, 1); cp_commit();

    float acc[4][4][4];
#pragma unroll
    for (int a = 0; a < 4; a++)
#pragma unroll
        for (int b = 0; b < 4; b++)
#pragma unroll
            for (int c = 0; c < 4; c++) acc[a][b][c] = 0.0f;

    // ldmatrix per-lane row/chunk decomposition (precompute bases)
    int ra = lane & 15, ca = lane >> 4;                    // A: 16 rows x 2 k-chunks
    int rb = (lane & 7) + ((lane >> 4) << 3);              // B: 8+8 n-rows
    int cb2 = (lane >> 3) & 1;                             // B: k-chunk half
    uint32_t abase[4], bbase[2];
    int ax[4], bx[2];
#pragma unroll
    for (int mt = 0; mt < 4; mt++) {
        int row = wm * 64 + mt * 16 + ra;
        abase[mt] = (uint32_t)(row * 128);
        ax[mt] = row & 7;
    }
#pragma unroll
    for (int bt = 0; bt < 2; bt++) {
        int row = wn * 32 + bt * 16 + rb;
        bbase[bt] = (uint32_t)(B_OFF + row * 128);
        bx[bt] = row & 7;
    }

    // double-buffered fragments
    uint32_t af[2][4][4], bf[2][2][4];

#define LOAD_FRAGS(st_, ks_, buf_)                                            \
    do {                                                                      \
        _Pragma("unroll")                                                     \
        for (int mt = 0; mt < 4; mt++)                                        \
            ldm_x4(af[buf_][mt],                                              \
                   (st_) + abase[mt] + (uint32_t)((((ks_)*2 + ca) ^ ax[mt]) * 16)); \
        _Pragma("unroll")                                                     \
        for (int bt = 0; bt < 2; bt++)                                        \
            ldm_x4(bf[buf_][bt],                                              \
                   (st_) + bbase[bt] + (uint32_t)((((ks_)*2 + cb2) ^ bx[bt]) * 16)); \
    } while (0)

#define MMA_ALL(buf_)                                                         \
    do {                                                                      \
        _Pragma("unroll")                                                     \
        for (int mt = 0; mt < 4; mt++)                                        \
            _Pragma("unroll")                                                 \
            for (int nt = 0; nt < 4; nt++)                                    \
                mma16816(acc[mt][nt], af[buf_][mt],                           \
                         bf[buf_][nt >> 1][(nt & 1) * 2],                     \
                         bf[buf_][nt >> 1][(nt & 1) * 2 + 1]);                \
    } while (0)

    int cs = 0, ps = 2;   // compute stage / prefetch stage (mod 3)
    for (int kt = 0; kt < NKT; kt++) {
        cp_wait1();
        __syncthreads();
        uint32_t st = sb + cs * STAGE_BYTES;
        // load ks=0 fragments first
        LOAD_FRAGS(st, 0, 0);
        // prefetch-tile pointers for kt+2 (issued spread across the ks loop)
        bool docopy = (kt + 2 < NKT);
        const __half* pa = ga0 + (kt + 2) * BK;
        const __half* pb = gb0 + (kt + 2) * BK;
        uint32_t ab = arow + (uint32_t)(ps * STAGE_BYTES);
#pragma unroll
        for (int ks = 0; ks < 4; ks++) {
            if (docopy) {   // 2 cp16 per ks: smooth LSU/port usage
                uint32_t so = (uint32_t)(((ccb + ks) ^ (crow & 7)) * 16);
                cp16(ab + so, pa + ks * 8);
                cp16(ab + B_OFF + so, pb + ks * 8);
            }
            if (ks < 3) LOAD_FRAGS(st, ks + 1, (ks + 1) & 1);  // prefetch next frags
            MMA_ALL(ks & 1);                                    // consume current
        }
        cp_commit();
        cs = (cs == 2) ? 0 : cs + 1;
        ps = (ps == 2) ? 0 : ps + 1;
    }

    // -------- epilogue: direct float2 stores + bias --------
    int r4 = lane >> 2, c2 = (lane & 3) * 2;
#pragma unroll
    for (int nt = 0; nt < 4; nt++) {
        int n = n0 + wn * 32 + nt * 8 + c2;
        float2 bv = *reinterpret_cast<const float2*>(&bias[n]);
#pragma unroll
        for (int mt = 0; mt < 4; mt++) {
            int m = m0 + wm * 64 + mt * 16 + r4;
            float2 v0 = {acc[mt][nt][0] + bv.x, acc[mt][nt][1] + bv.y};
            float2 v1 = {acc[mt][nt][2] + bv.x, acc[mt][nt][3] + bv.y};
            *reinterpret_cast<float2*>(&out[(size_t)m * NDIM + n]) = v0;
            *reinterpret_cast<float2*>(&out[(size_t)(m + 8) * NDIM + n]) = v1;
        }
    }
}

// ============================================================
// launcher
// ============================================================
extern "C" void kernel_launch(void* const* d_in, const int* in_sizes, int n_in,
                              void* d_out, int out_size) {
    const float* x = (const float*)d_in[0];
    const float* W = (const float*)d_in[1];
    const float* bias = (const float*)d_in[2];
    const float* L = (const float*)d_in[3];
    const float* R = (const float*)d_in[4];
    float* out = (float*)d_out;

    cudaFuncSetAttribute(gemm_kernel, cudaFuncAttributeMaxDynamicSharedMemorySize, SMEM_TOTAL);

    cvt_kernel<<<(MDIM * KDIM) / 4 / 256, 256>>>(x);
    weff_kernel<<<NDIM / 16, 256>>>(W, L, R);
    gemm_kernel<<<GRID_GEMM, 256, SMEM_TOTAL>>>(bias, out);
}